// round 13
// baseline (speedup 1.0000x reference)
#include <cuda_runtime.h>
#include <cuda_fp16.h>
#include <cstdint>

#define BB   32
#define CIN  32
#define HCC  64
#define HH   64
#define WW   64
#define CTOT 96
#define NGATE 256        // n = hc*4 + gate
#define NITER 27

// ---------------- device scratch ----------------
__device__ __half g_A[(size_t)BB * HH * WW * CTOT];  // [b][y][x][c] natural order fp16
__device__ __half g_W[NITER * NGATE * 32];           // [tap*3+kc][hc*4+gate][ci]
__device__ float  g_bias[NGATE];

__device__ __forceinline__ void cp_async16(uint32_t dst, const void* src, uint32_t sz) {
    asm volatile("cp.async.cg.shared.global [%0], [%1], 16, %2;"
                 :: "r"(dst), "l"(src), "r"(sz) : "memory");
}
__device__ __forceinline__ uint32_t smem_u32(const void* p) {
    uint32_t a;
    asm("{ .reg .u64 t; cvta.to.shared.u64 t, %1; cvt.u32.u64 %0, t; }" : "=r"(a) : "l"(p));
    return a;
}
#define CP_COMMIT() asm volatile("cp.async.commit_group;" ::: "memory")
#define CP_WAIT(n)  asm volatile("cp.async.wait_group %0;" :: "n"(n) : "memory")
#define BAR_PAIR(id) asm volatile("bar.sync %0, 64;" :: "r"(id) : "memory")

__device__ __forceinline__ void ldm4(uint32_t* r, uint32_t addr) {
    asm volatile("ldmatrix.sync.aligned.m8n8.x4.shared.b16 {%0,%1,%2,%3}, [%4];"
                 : "=r"(r[0]), "=r"(r[1]), "=r"(r[2]), "=r"(r[3]) : "r"(addr));
}
__device__ __forceinline__ void mma_f16(float* d, uint32_t a0, uint32_t a1, uint32_t a2,
                                        uint32_t a3, uint32_t b0, uint32_t b1) {
    asm volatile(
        "mma.sync.aligned.m16n8k16.row.col.f32.f16.f16.f32 "
        "{%0,%1,%2,%3}, {%4,%5,%6,%7}, {%8,%9}, {%0,%1,%2,%3};"
        : "+f"(d[0]), "+f"(d[1]), "+f"(d[2]), "+f"(d[3])
        : "r"(a0), "r"(a1), "r"(a2), "r"(a3), "r"(b0), "r"(b1));
}
__device__ __forceinline__ float fsigmoid(float v) {
    float e; asm("ex2.approx.f32 %0, %1;" : "=f"(e) : "f"(-v * 1.4426950408889634f));
    float r; asm("rcp.approx.f32 %0, %1;" : "=f"(r) : "f"(1.0f + e));
    return r;
}
__device__ __forceinline__ float ftanh(float v) {
    float e; asm("ex2.approx.f32 %0, %1;" : "=f"(e) : "f"(v * 2.885390081777927f));
    float r; asm("rcp.approx.f32 %0, %1;" : "=f"(r) : "f"(1.0f + e));
    return 1.0f - 2.0f * r;
}

// ---------------- merged pre-pass (natural channel order) ----------------
__global__ __launch_bounds__(256) void pack_all(
    const float* __restrict__ x, const float* __restrict__ hs,
    const float* wxi, const float* wxf, const float* wxo, const float* wxg,
    const float* whi, const float* whf, const float* who, const float* whg,
    const float* bxi, const float* bxf, const float* bxo, const float* bxg,
    const float* bhi, const float* bhf, const float* bho, const float* bhg) {
    const int blk = blockIdx.x;
    const int t = threadIdx.x;
    if (blk < 2048) {
        __shared__ float sm[CTOT * 65];
        int b = blk >> 6, y = blk & 63;
        #pragma unroll
        for (int i = 0; i < 6; i++) {
            int u = t + i * 256;
            int c = u >> 4, x4 = (u & 15) * 4;
            const float* src = (c < CIN)
                ? x  + ((size_t)(b * CIN + c) * HH + y) * WW + x4
                : hs + ((size_t)(b * HCC + (c - CIN)) * HH + y) * WW + x4;
            float4 v = *(const float4*)src;
            float* d = sm + c * 65 + x4;
            d[0] = v.x; d[1] = v.y; d[2] = v.z; d[3] = v.w;
        }
        __syncthreads();
        __half* dst = g_A + (size_t)(b * HH + y) * WW * CTOT;
        int o = t, xp = t / 96, cpos = t - xp * 96;
        #pragma unroll
        for (int k = 0; k < 24; k++) {
            dst[o] = __float2half_rn(sm[cpos * 65 + xp]);
            o += 256; cpos += 64; xp += 2;
            if (cpos >= 96) { cpos -= 96; xp += 1; }
        }
    } else if (blk < 2912) {
        const float* wx[4] = {wxi, wxf, wxo, wxg};
        const float* wh[4] = {whi, whf, who, whg};
        int g = (blk - 2048) * 256 + t;
        int ci = g & 31;
        int r = g >> 5;
        int n = r & 255;
        int tk = r >> 8;
        int tap = tk / 3, kc = tk - 3 * tap;
        int ky = tap / 3, kx = tap - 3 * ky;
        int hc = n >> 2, gate = n & 3;
        int cg = kc * 32 + ci;
        float v;
        if (cg < CIN) v = wx[gate][((hc * CIN + cg) * 3 + ky) * 3 + kx];
        else          v = wh[gate][((hc * HCC + (cg - CIN)) * 3 + ky) * 3 + kx];
        g_W[g] = __float2half_rn(v);
    } else {
        const float* bx[4] = {bxi, bxf, bxo, bxg};
        const float* bh[4] = {bhi, bhf, bho, bhg};
        int hc = t >> 2, gate = t & 3;
        g_bias[t] = bx[gate][hc] + bh[gate][hc];
    }
}

// ---------------- main kernel ----------------
#define AROWB 208                               // A row stride: 96ch*2B + 16B pad
#define A_TOTAL (4 * 66 * AROWB)                // 54912
#define BROWB 80
#define B_SLICE_B (32 * BROWB)                  // 2560 bytes: one pair-stage slice
#define SMEM_BYTES (A_TOTAL + 12 * B_SLICE_B)   // 85632 -> 2 CTAs/SM

__global__ __launch_bounds__(256, 2) void convlstm_mma(
    const float* __restrict__ cs, float* __restrict__ hout, float* __restrict__ cout) {
    extern __shared__ __half smh[];
    const uint32_t sb = smem_u32(smh);
    const int tid  = threadIdx.x;
    const int lane = tid & 31;
    const int wid  = tid >> 5;
    const int gid  = lane >> 2;
    const int tig  = lane & 3;
    const int warp_m = (wid >> 2) * 64;        // 2 warps over M (128)
    const int warpY  = warp_m >> 6;
    const int nI     = wid & 3;                // pair index 0..3
    const int warp_n = nI * 32;                // 4 warp-pairs over N (128)
    const int pairLane = warpY * 32 + lane;    // 0..63 within pair

    const int bx = blockIdx.x;
    const int nb = bx & 1;                     // N-half: hc [nb*32, nb*32+32)
    const int b  = bx >> 6;
    const int y0 = ((bx >> 1) & 31) * 2;
    const __half* Ab = g_A + (size_t)b * HH * WW * CTOT;

    // ldmatrix lane address offsets (bytes)
    const uint32_t laneA = (uint32_t)(((lane & 7) + ((lane >> 3) & 1) * 8) * AROWB
                                      + (lane >> 4) * 16);
    const uint32_t laneB = (uint32_t)((((lane >> 4) * 8) + (lane & 7)) * BROWB
                                      + ((lane >> 3) & 1) * 16);

    float acc[4][4][4];
    #pragma unroll
    for (int mi = 0; mi < 4; mi++)
        #pragma unroll
        for (int ni = 0; ni < 4; ni++)
            #pragma unroll
            for (int q = 0; q < 4; q++) acc[mi][ni][q] = 0.0f;

    // per-pair B prefetch: this pair's 32 rows x 32 ch of iteration `it`
    auto prefetchB = [&](int it, int s) {
        const __half* Wsrc = g_W + (size_t)it * (NGATE * 32)
                           + (size_t)(nb * 128 + warp_n) * 32;
        const uint32_t bb = sb + A_TOTAL + (uint32_t)((nI * 3 + s) * B_SLICE_B);
        #pragma unroll
        for (int u = 0; u < 2; u++) {
            int c = pairLane + u * 64;         // 0..127
            int r = c >> 2, j = c & 3;         // r 0..31
            cp_async16(bb + (uint32_t)(r * BROWB + j * 16), Wsrc + r * 32 + j * 8, 16u);
        }
        CP_COMMIT();
    };

    // A-resident fill: 4 rows x 66 cols x 96 ch (12 chunks of 16B per pixel)
    for (int i = tid; i < 3168; i += 256) {
        int j = i % 12;
        int rest = i / 12;                     // 0..263
        int xx = rest % 66;
        int yy = rest / 66;                    // 0..3
        int gy = y0 + yy - 1, gx = xx - 1;
        bool ok = ((unsigned)gy < HH) && ((unsigned)gx < WW);
        const __half* src = ok ? (Ab + ((size_t)(gy * WW + gx)) * CTOT + j * 8) : Ab;
        cp_async16(sb + (uint32_t)((yy * 66 + xx) * AROWB + j * 16), src, ok ? 16u : 0u);
    }
    CP_COMMIT();
    prefetchB(0, 0);
    prefetchB(1, 1);

    int kc = 0, ky = 0, kx = 0;
    for (int it = 0; it < NITER; it++) {
        // commit next stage first, then drain the stage we consume now
        if (it + 2 < NITER) prefetchB(it + 2, (it + 2) % 3);
        if (it + 2 < NITER)      { CP_WAIT(2); }
        else if (it + 1 < NITER) { CP_WAIT(1); }
        else                     { CP_WAIT(0); }
        if (it == 0) __syncthreads();          // publishes shared A region (and B0)
        else BAR_PAIR(1 + nI);                 // 2-warp pair barrier publishes B(it)
        const int s = it % 3;

        const uint32_t aBase = sb + (uint32_t)(((warpY + ky) * 66 + kx) * AROWB + kc * 64)
                             + laneA;
        const uint32_t bBase = sb + A_TOTAL + (uint32_t)((nI * 3 + s) * B_SLICE_B)
                             + laneB;

        uint32_t a[2][4][4];
        uint32_t b01[2][4], b23[2][4];
        #pragma unroll
        for (int kh = 0; kh < 2; kh++) {
            const uint32_t kb = (uint32_t)(kh * 32);   // k16 step = 32 bytes
            #pragma unroll
            for (int mi = 0; mi < 4; mi++)
                ldm4(a[kh][mi], aBase + (uint32_t)(mi * 16 * AROWB) + kb);
            ldm4(b01[kh], bBase + kb);
            ldm4(b23[kh], bBase + (uint32_t)(16 * BROWB) + kb);
        }
        #pragma unroll
        for (int kh = 0; kh < 2; kh++) {
            #pragma unroll
            for (int mi = 0; mi < 4; mi++) {
                mma_f16(acc[mi][0], a[kh][mi][0], a[kh][mi][1], a[kh][mi][2], a[kh][mi][3],
                        b01[kh][0], b01[kh][1]);
                mma_f16(acc[mi][1], a[kh][mi][0], a[kh][mi][1], a[kh][mi][2], a[kh][mi][3],
                        b01[kh][2], b01[kh][3]);
                mma_f16(acc[mi][2], a[kh][mi][0], a[kh][mi][1], a[kh][mi][2], a[kh][mi][3],
                        b23[kh][0], b23[kh][1]);
                mma_f16(acc[mi][3], a[kh][mi][0], a[kh][mi][1], a[kh][mi][2], a[kh][mi][3],
                        b23[kh][2], b23[kh][3]);
            }
        }

        if (++kc == 3) { kc = 0; if (++kx == 3) { kx = 0; ky++; } }
    }

    // ---- fused LSTM epilogue (cs loads batched per mi-row) ----
    const int odd = tig & 1;
    #pragma unroll
    for (int mi = 0; mi < 4; mi++) {
        const int rowE = warp_m + mi * 16 + gid;          // even-lane row
        const int row  = odd ? rowE + 8 : rowE;
        const int y = y0 + (row >> 6);
        const int x = row & 63;
        int  cidx[4];
        float csv[4];
        #pragma unroll
        for (int ni = 0; ni < 4; ni++) {
            const int hc = nb * 32 + (warp_n >> 2) + ni * 2 + (tig >> 1);
            cidx[ni] = ((b * HCC + hc) * HH + y) * WW + x;
            csv[ni] = cs[cidx[ni]];
        }
        #pragma unroll
        for (int ni = 0; ni < 4; ni++) {
            float c0 = acc[mi][ni][0], c1 = acc[mi][ni][1];
            float c2 = acc[mi][ni][2], c3 = acc[mi][ni][3];
            float e0 = __shfl_xor_sync(0xFFFFFFFFu, odd ? c0 : c2, 1);
            float e1 = __shfl_xor_sync(0xFFFFFFFFu, odd ? c1 : c3, 1);
            float zi, zf, zo, zg;
            if (!odd) { zi = c0; zf = c1; zo = e0; zg = e1; }
            else      { zi = e0; zf = e1; zo = c2; zg = c3; }
            const int hc = nb * 32 + (warp_n >> 2) + ni * 2 + (tig >> 1);
            const float4 bv = *(const float4*)(g_bias + hc * 4);
            zi += bv.x; zf += bv.y; zo += bv.z; zg += bv.w;
            float ig = fsigmoid(zi), fg = fsigmoid(zf), og = fsigmoid(zo);
            float gg = ftanh(zg);
            float cn = fg * csv[ni] + ig * gg;
            hout[cidx[ni]] = og * ftanh(cn);
            cout[cidx[ni]] = cn;
        }
    }
}

// ---------------- host ----------------
extern "C" void kernel_launch(void* const* d_in, const int* in_sizes, int n_in,
                              void* d_out, int out_size) {
    const float* x  = (const float*)d_in[0];
    const float* hs = (const float*)d_in[1];
    const float* cs = (const float*)d_in[2];

    const float *WX[4], *BX[4], *WH[4], *BH[4];
    if (in_sizes[4] == HCC) {
        for (int g = 0; g < 4; g++) {
            WX[g] = (const float*)d_in[3 + 2 * g];
            BX[g] = (const float*)d_in[4 + 2 * g];
            WH[g] = (const float*)d_in[11 + 2 * g];
            BH[g] = (const float*)d_in[12 + 2 * g];
        }
    } else {
        for (int g = 0; g < 4; g++) {
            WX[g] = (const float*)d_in[3 + g];
            BX[g] = (const float*)d_in[7 + g];
            WH[g] = (const float*)d_in[11 + g];
            BH[g] = (const float*)d_in[15 + g];
        }
    }

    float* hout = (float*)d_out;
    float* cout = hout + (size_t)BB * HCC * HH * WW;

    pack_all<<<2913, 256>>>(x, hs,
        WX[0], WX[1], WX[2], WX[3], WH[0], WH[1], WH[2], WH[3],
        BX[0], BX[1], BX[2], BX[3], BH[0], BH[1], BH[2], BH[3]);

    cudaFuncSetAttribute(convlstm_mma, cudaFuncAttributeMaxDynamicSharedMemorySize, SMEM_BYTES);
    convlstm_mma<<<2048, 256, SMEM_BYTES>>>(cs, hout, cout);
}

// round 16
// speedup vs baseline: 1.0206x; 1.0206x over previous
#include <cuda_runtime.h>
#include <cuda_fp16.h>
#include <cstdint>

#define BB   32
#define CIN  32
#define HCC  64
#define HH   64
#define WW   64
#define CTOT 96
#define NGATE 256        // n = hc*4 + gate
#define NITER 27

// ---------------- device scratch ----------------
__device__ __half g_A[(size_t)BB * HH * WW * CTOT];  // [b][y][x][c] natural order fp16
__device__ __half g_W[NITER * NGATE * 32];           // [tap*3+kc][hc*4+gate][ci]
__device__ float  g_bias[NGATE];

__device__ __forceinline__ void cp_async16(uint32_t dst, const void* src, uint32_t sz) {
    asm volatile("cp.async.cg.shared.global [%0], [%1], 16, %2;"
                 :: "r"(dst), "l"(src), "r"(sz) : "memory");
}
__device__ __forceinline__ uint32_t smem_u32(const void* p) {
    uint32_t a;
    asm("{ .reg .u64 t; cvta.to.shared.u64 t, %1; cvt.u32.u64 %0, t; }" : "=r"(a) : "l"(p));
    return a;
}
#define CP_COMMIT() asm volatile("cp.async.commit_group;" ::: "memory")
#define CP_WAIT(n)  asm volatile("cp.async.wait_group %0;" :: "n"(n) : "memory")

__device__ __forceinline__ void ldm4(uint32_t* r, uint32_t addr) {
    asm volatile("ldmatrix.sync.aligned.m8n8.x4.shared.b16 {%0,%1,%2,%3}, [%4];"
                 : "=r"(r[0]), "=r"(r[1]), "=r"(r[2]), "=r"(r[3]) : "r"(addr));
}
__device__ __forceinline__ void mma_f16(float* d, uint32_t a0, uint32_t a1, uint32_t a2,
                                        uint32_t a3, uint32_t b0, uint32_t b1) {
    asm volatile(
        "mma.sync.aligned.m16n8k16.row.col.f32.f16.f16.f32 "
        "{%0,%1,%2,%3}, {%4,%5,%6,%7}, {%8,%9}, {%0,%1,%2,%3};"
        : "+f"(d[0]), "+f"(d[1]), "+f"(d[2]), "+f"(d[3])
        : "r"(a0), "r"(a1), "r"(a2), "r"(a3), "r"(b0), "r"(b1));
}
__device__ __forceinline__ float fsigmoid(float v) {
    float e; asm("ex2.approx.f32 %0, %1;" : "=f"(e) : "f"(-v * 1.4426950408889634f));
    float r; asm("rcp.approx.f32 %0, %1;" : "=f"(r) : "f"(1.0f + e));
    return r;
}
__device__ __forceinline__ float ftanh(float v) {
    float e; asm("ex2.approx.f32 %0, %1;" : "=f"(e) : "f"(v * 2.885390081777927f));
    float r; asm("rcp.approx.f32 %0, %1;" : "=f"(r) : "f"(1.0f + e));
    return 1.0f - 2.0f * r;
}

// ---------------- merged pre-pass (natural channel order) ----------------
__global__ __launch_bounds__(256) void pack_all(
    const float* __restrict__ x, const float* __restrict__ hs,
    const float* wxi, const float* wxf, const float* wxo, const float* wxg,
    const float* whi, const float* whf, const float* who, const float* whg,
    const float* bxi, const float* bxf, const float* bxo, const float* bxg,
    const float* bhi, const float* bhf, const float* bho, const float* bhg) {
    const int blk = blockIdx.x;
    const int t = threadIdx.x;
    if (blk < 2048) {
        __shared__ float sm[CTOT * 65];
        int b = blk >> 6, y = blk & 63;
        #pragma unroll
        for (int i = 0; i < 6; i++) {
            int u = t + i * 256;
            int c = u >> 4, x4 = (u & 15) * 4;
            const float* src = (c < CIN)
                ? x  + ((size_t)(b * CIN + c) * HH + y) * WW + x4
                : hs + ((size_t)(b * HCC + (c - CIN)) * HH + y) * WW + x4;
            float4 v = *(const float4*)src;
            float* d = sm + c * 65 + x4;
            d[0] = v.x; d[1] = v.y; d[2] = v.z; d[3] = v.w;
        }
        __syncthreads();
        // phase 2: vectorized — each unit = 8 consecutive channels of one pixel
        // 64 px * 12 groups = 768 units; 3 per thread; one uint4 store each
        uint4* dst = (uint4*)(g_A + (size_t)(b * HH + y) * WW * CTOT);
        #pragma unroll
        for (int i = 0; i < 3; i++) {
            int u = t + i * 256;               // 0..767
            int xp = u / 12, grp = u - xp * 12;
            const float* sp = sm + (grp * 8) * 65 + xp;
            __half h[8];
            #pragma unroll
            for (int j = 0; j < 8; j++) h[j] = __float2half_rn(sp[j * 65]);
            dst[u] = *(const uint4*)h;
        }
    } else if (blk < 2912) {
        const float* wx[4] = {wxi, wxf, wxo, wxg};
        const float* wh[4] = {whi, whf, who, whg};
        int g = (blk - 2048) * 256 + t;
        int ci = g & 31;
        int r = g >> 5;
        int n = r & 255;
        int tk = r >> 8;
        int tap = tk / 3, kc = tk - 3 * tap;
        int ky = tap / 3, kx = tap - 3 * ky;
        int hc = n >> 2, gate = n & 3;
        int cg = kc * 32 + ci;
        float v;
        if (cg < CIN) v = wx[gate][((hc * CIN + cg) * 3 + ky) * 3 + kx];
        else          v = wh[gate][((hc * HCC + (cg - CIN)) * 3 + ky) * 3 + kx];
        g_W[g] = __float2half_rn(v);
    } else {
        const float* bx[4] = {bxi, bxf, bxo, bxg};
        const float* bh[4] = {bhi, bhf, bho, bhg};
        int hc = t >> 2, gate = t & 3;
        g_bias[t] = bx[gate][hc] + bh[gate][hc];
    }
}

// ---------------- main kernel (R10 structure) ----------------
#define AROWB 208                               // A row stride: 96ch*2B + 16B pad
#define A_TOTAL (4 * 66 * AROWB)                // 54912
#define BROWB 80
#define B_STAGE_B (128 * BROWB)                 // 10240
#define SMEM_BYTES (A_TOTAL + 4 * B_STAGE_B)    // 95872 -> 2 CTAs/SM

__global__ __launch_bounds__(256, 2) void convlstm_mma(
    const float* __restrict__ cs, float* __restrict__ hout, float* __restrict__ cout) {
    extern __shared__ __half smh[];
    const uint32_t sb = smem_u32(smh);
    const int tid  = threadIdx.x;
    const int lane = tid & 31;
    const int wid  = tid >> 5;
    const int gid  = lane >> 2;
    const int tig  = lane & 3;
    const int warp_m = (wid >> 2) * 64;        // 2 warps over M (128)
    const int warpY  = warp_m >> 6;
    const int warp_n = (wid & 3) * 32;         // 4 warps over N (128)

    const int bx = blockIdx.x;
    const int nb = bx & 1;                     // N-half: hc [nb*32, nb*32+32)
    const int b  = bx >> 6;
    const int y0 = ((bx >> 1) & 31) * 2;
    const __half* Ab = g_A + (size_t)b * HH * WW * CTOT;

    const uint32_t laneA = (uint32_t)(((lane & 7) + ((lane >> 3) & 1) * 8) * AROWB
                                      + (lane >> 4) * 16);
    const uint32_t laneB = (uint32_t)((((lane >> 4) * 8) + (lane & 7)) * BROWB
                                      + ((lane >> 3) & 1) * 16);

    float acc[4][4][4];
    #pragma unroll
    for (int mi = 0; mi < 4; mi++)
        #pragma unroll
        for (int ni = 0; ni < 4; ni++)
            #pragma unroll
            for (int q = 0; q < 4; q++) acc[mi][ni][q] = 0.0f;

    auto prefetchB = [&](int it, int s) {
        const __half* Wsrc = g_W + (size_t)it * (NGATE * 32) + nb * (128 * 32);
        const uint32_t bb = sb + A_TOTAL + (uint32_t)s * B_STAGE_B;
        #pragma unroll
        for (int u = 0; u < 2; u++) {
            int c = tid + u * 256;             // 0..511
            int r = c >> 2, j = c & 3;         // r 0..127
            cp_async16(bb + (uint32_t)(r * BROWB + j * 16), Wsrc + r * 32 + j * 8, 16u);
        }
        CP_COMMIT();
    };

    // A-resident fill: 4 rows x 66 cols x 96 ch (12 chunks of 16B per pixel)
    for (int i = tid; i < 3168; i += 256) {
        int j = i % 12;
        int rest = i / 12;                     // 0..263
        int xx = rest % 66;
        int yy = rest / 66;                    // 0..3
        int gy = y0 + yy - 1, gx = xx - 1;
        bool ok = ((unsigned)gy < HH) && ((unsigned)gx < WW);
        const __half* src = ok ? (Ab + ((size_t)(gy * WW + gx)) * CTOT + j * 8) : Ab;
        cp_async16(sb + (uint32_t)((yy * 66 + xx) * AROWB + j * 16), src, ok ? 16u : 0u);
    }
    CP_COMMIT();
    prefetchB(0, 0);
    prefetchB(1, 1);

    int kc = 0, ky = 0, kx = 0;
    for (int it = 0; it < NITER; it++) {
        if ((it & 1) == 0) {
            CP_WAIT(0);                 // drain own groups (publishes P(it),P(it+1))
            __syncthreads();            // cross-thread visibility for both stages
            if (it + 2 < NITER) prefetchB(it + 2, (it + 2) & 3);
        } else {
            if (it + 2 < NITER) prefetchB(it + 2, (it + 2) & 3);
        }
        const int s = it & 3;

        const uint32_t aBase = sb + (uint32_t)(((warpY + ky) * 66 + kx) * AROWB + kc * 64)
                             + laneA;
        const uint32_t bBase = sb + A_TOTAL + (uint32_t)(s * B_STAGE_B + warp_n * BROWB)
                             + laneB;

        #pragma unroll
        for (int kh = 0; kh < 2; kh++) {
            const uint32_t kb = (uint32_t)(kh * 32);   // k16 step = 32 bytes
            uint32_t a[4][4];
            #pragma unroll
            for (int mi = 0; mi < 4; mi++)
                ldm4(a[mi], aBase + (uint32_t)(mi * 16 * AROWB) + kb);
            uint32_t b01[4], b23[4];
            ldm4(b01, bBase + kb);
            ldm4(b23, bBase + (uint32_t)(16 * BROWB) + kb);

            #pragma unroll
            for (int mi = 0; mi < 4; mi++) {
                mma_f16(acc[mi][0], a[mi][0], a[mi][1], a[mi][2], a[mi][3], b01[0], b01[1]);
                mma_f16(acc[mi][1], a[mi][0], a[mi][1], a[mi][2], a[mi][3], b01[2], b01[3]);
                mma_f16(acc[mi][2], a[mi][0], a[mi][1], a[mi][2], a[mi][3], b23[0], b23[1]);
                mma_f16(acc[mi][3], a[mi][0], a[mi][1], a[mi][2], a[mi][3], b23[2], b23[3]);
            }
        }

        if (++kc == 3) { kc = 0; if (++kx == 3) { kx = 0; ky++; } }
    }

    // ---- fused LSTM epilogue: ALL 16 cs loads issued up front (MLP=16) ----
    const int odd = tig & 1;
    int   cidx[4][4];
    float csv[4][4];
    #pragma unroll
    for (int mi = 0; mi < 4; mi++) {
        const int rowE = warp_m + mi * 16 + gid;
        const int row  = odd ? rowE + 8 : rowE;
        const int y = y0 + (row >> 6);
        const int x = row & 63;
        #pragma unroll
        for (int ni = 0; ni < 4; ni++) {
            const int hc = nb * 32 + (warp_n >> 2) + ni * 2 + (tig >> 1);
            cidx[mi][ni] = ((b * HCC + hc) * HH + y) * WW + x;
        }
    }
    #pragma unroll
    for (int mi = 0; mi < 4; mi++)
        #pragma unroll
        for (int ni = 0; ni < 4; ni++)
            csv[mi][ni] = cs[cidx[mi][ni]];

    #pragma unroll
    for (int mi = 0; mi < 4; mi++) {
        #pragma unroll
        for (int ni = 0; ni < 4; ni++) {
            float c0 = acc[mi][ni][0], c1 = acc[mi][ni][1];
            float c2 = acc[mi][ni][2], c3 = acc[mi][ni][3];
            float e0 = __shfl_xor_sync(0xFFFFFFFFu, odd ? c0 : c2, 1);
            float e1 = __shfl_xor_sync(0xFFFFFFFFu, odd ? c1 : c3, 1);
            float zi, zf, zo, zg;
            if (!odd) { zi = c0; zf = c1; zo = e0; zg = e1; }
            else      { zi = e0; zf = e1; zo = c2; zg = c3; }
            const int hc = nb * 32 + (warp_n >> 2) + ni * 2 + (tig >> 1);
            const float4 bv = *(const float4*)(g_bias + hc * 4);
            zi += bv.x; zf += bv.y; zo += bv.z; zg += bv.w;
            float ig = fsigmoid(zi), fg = fsigmoid(zf), og = fsigmoid(zo);
            float gg = ftanh(zg);
            float cn = fg * csv[mi][ni] + ig * gg;
            hout[cidx[mi][ni]] = og * ftanh(cn);
            cout[cidx[mi][ni]] = cn;
        }
    }
}

// ---------------- host ----------------
extern "C" void kernel_launch(void* const* d_in, const int* in_sizes, int n_in,
                              void* d_out, int out_size) {
    const float* x  = (const float*)d_in[0];
    const float* hs = (const float*)d_in[1];
    const float* cs = (const float*)d_in[2];

    const float *WX[4], *BX[4], *WH[4], *BH[4];
    if (in_sizes[4] == HCC) {
        for (int g = 0; g < 4; g++) {
            WX[g] = (const float*)d_in[3 + 2 * g];
            BX[g] = (const float*)d_in[4 + 2 * g];
            WH[g] = (const float*)d_in[11 + 2 * g];
            BH[g] = (const float*)d_in[12 + 2 * g];
        }
    } else {
        for (int g = 0; g < 4; g++) {
            WX[g] = (const float*)d_in[3 + g];
            BX[g] = (const float*)d_in[7 + g];
            WH[g] = (const float*)d_in[11 + g];
            BH[g] = (const float*)d_in[15 + g];
        }
    }

    float* hout = (float*)d_out;
    float* cout = hout + (size_t)BB * HCC * HH * WW;

    pack_all<<<2913, 256>>>(x, hs,
        WX[0], WX[1], WX[2], WX[3], WH[0], WH[1], WH[2], WH[3],
        BX[0], BX[1], BX[2], BX[3], BH[0], BH[1], BH[2], BH[3]);

    cudaFuncSetAttribute(convlstm_mma, cudaFuncAttributeMaxDynamicSharedMemorySize, SMEM_BYTES);
    convlstm_mma<<<2048, 256, SMEM_BYTES>>>(cs, hout, cout);
}

// round 17
// speedup vs baseline: 1.0346x; 1.0138x over previous
#include <cuda_runtime.h>
#include <cuda_fp16.h>
#include <cstdint>

#define BB   32
#define CIN  32
#define HCC  64
#define HH   64
#define WW   64
#define CTOT 96
#define NGATE 256        // n = hc*4 + gate
#define NITER 27

// ---------------- device scratch ----------------
__device__ __half g_A[(size_t)BB * HH * WW * CTOT];  // [b][y][x][c] natural order fp16
__device__ __half g_W[NITER * NGATE * 32];           // [tap*3+kc][hc*4+gate][ci]
__device__ float  g_bias[NGATE];

__device__ __forceinline__ void cp_async16(uint32_t dst, const void* src, uint32_t sz) {
    asm volatile("cp.async.cg.shared.global [%0], [%1], 16, %2;"
                 :: "r"(dst), "l"(src), "r"(sz) : "memory");
}
__device__ __forceinline__ uint32_t smem_u32(const void* p) {
    uint32_t a;
    asm("{ .reg .u64 t; cvta.to.shared.u64 t, %1; cvt.u32.u64 %0, t; }" : "=r"(a) : "l"(p));
    return a;
}
#define CP_COMMIT() asm volatile("cp.async.commit_group;" ::: "memory")
#define CP_WAIT(n)  asm volatile("cp.async.wait_group %0;" :: "n"(n) : "memory")

__device__ __forceinline__ void ldm4(uint32_t* r, uint32_t addr) {
    asm volatile("ldmatrix.sync.aligned.m8n8.x4.shared.b16 {%0,%1,%2,%3}, [%4];"
                 : "=r"(r[0]), "=r"(r[1]), "=r"(r[2]), "=r"(r[3]) : "r"(addr));
}
__device__ __forceinline__ void mma_f16(float* d, uint32_t a0, uint32_t a1, uint32_t a2,
                                        uint32_t a3, uint32_t b0, uint32_t b1) {
    asm volatile(
        "mma.sync.aligned.m16n8k16.row.col.f32.f16.f16.f32 "
        "{%0,%1,%2,%3}, {%4,%5,%6,%7}, {%8,%9}, {%0,%1,%2,%3};"
        : "+f"(d[0]), "+f"(d[1]), "+f"(d[2]), "+f"(d[3])
        : "r"(a0), "r"(a1), "r"(a2), "r"(a3), "r"(b0), "r"(b1));
}
__device__ __forceinline__ float fsigmoid(float v) {
    float e; asm("ex2.approx.f32 %0, %1;" : "=f"(e) : "f"(-v * 1.4426950408889634f));
    float r; asm("rcp.approx.f32 %0, %1;" : "=f"(r) : "f"(1.0f + e));
    return r;
}
__device__ __forceinline__ float ftanh(float v) {
    float e; asm("ex2.approx.f32 %0, %1;" : "=f"(e) : "f"(v * 2.885390081777927f));
    float r; asm("rcp.approx.f32 %0, %1;" : "=f"(r) : "f"(1.0f + e));
    return 1.0f - 2.0f * r;
}

// ---------------- merged pre-pass (R10 scalar phase-2: measured fastest) -----------
__global__ __launch_bounds__(256) void pack_all(
    const float* __restrict__ x, const float* __restrict__ hs,
    const float* wxi, const float* wxf, const float* wxo, const float* wxg,
    const float* whi, const float* whf, const float* who, const float* whg,
    const float* bxi, const float* bxf, const float* bxo, const float* bxg,
    const float* bhi, const float* bhf, const float* bho, const float* bhg) {
    const int blk = blockIdx.x;
    const int t = threadIdx.x;
    if (blk < 2048) {
        __shared__ float sm[CTOT * 65];
        int b = blk >> 6, y = blk & 63;
        #pragma unroll
        for (int i = 0; i < 6; i++) {
            int u = t + i * 256;
            int c = u >> 4, x4 = (u & 15) * 4;
            const float* src = (c < CIN)
                ? x  + ((size_t)(b * CIN + c) * HH + y) * WW + x4
                : hs + ((size_t)(b * HCC + (c - CIN)) * HH + y) * WW + x4;
            float4 v = *(const float4*)src;
            float* d = sm + c * 65 + x4;
            d[0] = v.x; d[1] = v.y; d[2] = v.z; d[3] = v.w;
        }
        __syncthreads();
        __half* dst = g_A + (size_t)(b * HH + y) * WW * CTOT;
        int o = t, xp = t / 96, cpos = t - xp * 96;
        #pragma unroll
        for (int k = 0; k < 24; k++) {
            dst[o] = __float2half_rn(sm[cpos * 65 + xp]);
            o += 256; cpos += 64; xp += 2;
            if (cpos >= 96) { cpos -= 96; xp += 1; }
        }
    } else if (blk < 2912) {
        const float* wx[4] = {wxi, wxf, wxo, wxg};
        const float* wh[4] = {whi, whf, who, whg};
        int g = (blk - 2048) * 256 + t;
        int ci = g & 31;
        int r = g >> 5;
        int n = r & 255;
        int tk = r >> 8;
        int tap = tk / 3, kc = tk - 3 * tap;
        int ky = tap / 3, kx = tap - 3 * ky;
        int hc = n >> 2, gate = n & 3;
        int cg = kc * 32 + ci;
        float v;
        if (cg < CIN) v = wx[gate][((hc * CIN + cg) * 3 + ky) * 3 + kx];
        else          v = wh[gate][((hc * HCC + (cg - CIN)) * 3 + ky) * 3 + kx];
        g_W[g] = __float2half_rn(v);
    } else {
        const float* bx[4] = {bxi, bxf, bxo, bxg};
        const float* bh[4] = {bhi, bhf, bho, bhg};
        int hc = t >> 2, gate = t & 3;
        g_bias[t] = bx[gate][hc] + bh[gate][hc];
    }
}

// ---------------- main kernel (R16: R10 loop + batched-cs epilogue) ----------------
#define AROWB 208                               // A row stride: 96ch*2B + 16B pad
#define A_TOTAL (4 * 66 * AROWB)                // 54912
#define BROWB 80
#define B_STAGE_B (128 * BROWB)                 // 10240
#define SMEM_BYTES (A_TOTAL + 4 * B_STAGE_B)    // 95872 -> 2 CTAs/SM

__global__ __launch_bounds__(256, 2) void convlstm_mma(
    const float* __restrict__ cs, float* __restrict__ hout, float* __restrict__ cout) {
    extern __shared__ __half smh[];
    const uint32_t sb = smem_u32(smh);
    const int tid  = threadIdx.x;
    const int lane = tid & 31;
    const int wid  = tid >> 5;
    const int gid  = lane >> 2;
    const int tig  = lane & 3;
    const int warp_m = (wid >> 2) * 64;        // 2 warps over M (128)
    const int warpY  = warp_m >> 6;
    const int warp_n = (wid & 3) * 32;         // 4 warps over N (128)

    const int bx = blockIdx.x;
    const int nb = bx & 1;                     // N-half: hc [nb*32, nb*32+32)
    const int b  = bx >> 6;
    const int y0 = ((bx >> 1) & 31) * 2;
    const __half* Ab = g_A + (size_t)b * HH * WW * CTOT;

    const uint32_t laneA = (uint32_t)(((lane & 7) + ((lane >> 3) & 1) * 8) * AROWB
                                      + (lane >> 4) * 16);
    const uint32_t laneB = (uint32_t)((((lane >> 4) * 8) + (lane & 7)) * BROWB
                                      + ((lane >> 3) & 1) * 16);

    float acc[4][4][4];
    #pragma unroll
    for (int mi = 0; mi < 4; mi++)
        #pragma unroll
        for (int ni = 0; ni < 4; ni++)
            #pragma unroll
            for (int q = 0; q < 4; q++) acc[mi][ni][q] = 0.0f;

    auto prefetchB = [&](int it, int s) {
        const __half* Wsrc = g_W + (size_t)it * (NGATE * 32) + nb * (128 * 32);
        const uint32_t bb = sb + A_TOTAL + (uint32_t)s * B_STAGE_B;
        #pragma unroll
        for (int u = 0; u < 2; u++) {
            int c = tid + u * 256;             // 0..511
            int r = c >> 2, j = c & 3;         // r 0..127
            cp_async16(bb + (uint32_t)(r * BROWB + j * 16), Wsrc + r * 32 + j * 8, 16u);
        }
        CP_COMMIT();
    };

    // A-resident fill: 4 rows x 66 cols x 96 ch (12 chunks of 16B per pixel)
    for (int i = tid; i < 3168; i += 256) {
        int j = i % 12;
        int rest = i / 12;                     // 0..263
        int xx = rest % 66;
        int yy = rest / 66;                    // 0..3
        int gy = y0 + yy - 1, gx = xx - 1;
        bool ok = ((unsigned)gy < HH) && ((unsigned)gx < WW);
        const __half* src = ok ? (Ab + ((size_t)(gy * WW + gx)) * CTOT + j * 8) : Ab;
        cp_async16(sb + (uint32_t)((yy * 66 + xx) * AROWB + j * 16), src, ok ? 16u : 0u);
    }
    CP_COMMIT();
    prefetchB(0, 0);
    prefetchB(1, 1);

    int kc = 0, ky = 0, kx = 0;
    for (int it = 0; it < NITER; it++) {
        if ((it & 1) == 0) {
            CP_WAIT(0);                 // drain own groups (publishes P(it),P(it+1))
            __syncthreads();            // cross-thread visibility for both stages
            if (it + 2 < NITER) prefetchB(it + 2, (it + 2) & 3);
        } else {
            if (it + 2 < NITER) prefetchB(it + 2, (it + 2) & 3);
        }
        const int s = it & 3;

        const uint32_t aBase = sb + (uint32_t)(((warpY + ky) * 66 + kx) * AROWB + kc * 64)
                             + laneA;
        const uint32_t bBase = sb + A_TOTAL + (uint32_t)(s * B_STAGE_B + warp_n * BROWB)
                             + laneB;

        #pragma unroll
        for (int kh = 0; kh < 2; kh++) {
            const uint32_t kb = (uint32_t)(kh * 32);   // k16 step = 32 bytes
            uint32_t a[4][4];
            #pragma unroll
            for (int mi = 0; mi < 4; mi++)
                ldm4(a[mi], aBase + (uint32_t)(mi * 16 * AROWB) + kb);
            uint32_t b01[4], b23[4];
            ldm4(b01, bBase + kb);
            ldm4(b23, bBase + (uint32_t)(16 * BROWB) + kb);

            #pragma unroll
            for (int mi = 0; mi < 4; mi++) {
                mma_f16(acc[mi][0], a[mi][0], a[mi][1], a[mi][2], a[mi][3], b01[0], b01[1]);
                mma_f16(acc[mi][1], a[mi][0], a[mi][1], a[mi][2], a[mi][3], b01[2], b01[3]);
                mma_f16(acc[mi][2], a[mi][0], a[mi][1], a[mi][2], a[mi][3], b23[0], b23[1]);
                mma_f16(acc[mi][3], a[mi][0], a[mi][1], a[mi][2], a[mi][3], b23[2], b23[3]);
            }
        }

        if (++kc == 3) { kc = 0; if (++kx == 3) { kx = 0; ky++; } }
    }

    // ---- fused LSTM epilogue: ALL 16 cs loads issued up front (MLP=16) ----
    const int odd = tig & 1;
    int   cidx[4][4];
    float csv[4][4];
    #pragma unroll
    for (int mi = 0; mi < 4; mi++) {
        const int rowE = warp_m + mi * 16 + gid;
        const int row  = odd ? rowE + 8 : rowE;
        const int y = y0 + (row >> 6);
        const int x = row & 63;
        #pragma unroll
        for (int ni = 0; ni < 4; ni++) {
            const int hc = nb * 32 + (warp_n >> 2) + ni * 2 + (tig >> 1);
            cidx[mi][ni] = ((b * HCC + hc) * HH + y) * WW + x;
        }
    }
    #pragma unroll
    for (int mi = 0; mi < 4; mi++)
        #pragma unroll
        for (int ni = 0; ni < 4; ni++)
            csv[mi][ni] = cs[cidx[mi][ni]];

    #pragma unroll
    for (int mi = 0; mi < 4; mi++) {
        #pragma unroll
        for (int ni = 0; ni < 4; ni++) {
            float c0 = acc[mi][ni][0], c1 = acc[mi][ni][1];
            float c2 = acc[mi][ni][2], c3 = acc[mi][ni][3];
            float e0 = __shfl_xor_sync(0xFFFFFFFFu, odd ? c0 : c2, 1);
            float e1 = __shfl_xor_sync(0xFFFFFFFFu, odd ? c1 : c3, 1);
            float zi, zf, zo, zg;
            if (!odd) { zi = c0; zf = c1; zo = e0; zg = e1; }
            else      { zi = e0; zf = e1; zo = c2; zg = c3; }
            const int hc = nb * 32 + (warp_n >> 2) + ni * 2 + (tig >> 1);
            const float4 bv = *(const float4*)(g_bias + hc * 4);
            zi += bv.x; zf += bv.y; zo += bv.z; zg += bv.w;
            float ig = fsigmoid(zi), fg = fsigmoid(zf), og = fsigmoid(zo);
            float gg = ftanh(zg);
            float cn = fg * csv[mi][ni] + ig * gg;
            hout[cidx[mi][ni]] = og * ftanh(cn);
            cout[cidx[mi][ni]] = cn;
        }
    }
}

// ---------------- host ----------------
extern "C" void kernel_launch(void* const* d_in, const int* in_sizes, int n_in,
                              void* d_out, int out_size) {
    const float* x  = (const float*)d_in[0];
    const float* hs = (const float*)d_in[1];
    const float* cs = (const float*)d_in[2];

    const float *WX[4], *BX[4], *WH[4], *BH[4];
    if (in_sizes[4] == HCC) {
        for (int g = 0; g < 4; g++) {
            WX[g] = (const float*)d_in[3 + 2 * g];
            BX[g] = (const float*)d_in[4 + 2 * g];
            WH[g] = (const float*)d_in[11 + 2 * g];
            BH[g] = (const float*)d_in[12 + 2 * g];
        }
    } else {
        for (int g = 0; g < 4; g++) {
            WX[g] = (const float*)d_in[3 + g];
            BX[g] = (const float*)d_in[7 + g];
            WH[g] = (const float*)d_in[11 + g];
            BH[g] = (const float*)d_in[15 + g];
        }
    }

    float* hout = (float*)d_out;
    float* cout = hout + (size_t)BB * HCC * HH * WW;

    pack_all<<<2913, 256>>>(x, hs,
        WX[0], WX[1], WX[2], WX[3], WH[0], WH[1], WH[2], WH[3],
        BX[0], BX[1], BX[2], BX[3], BH[0], BH[1], BH[2], BH[3]);

    cudaFuncSetAttribute(convlstm_mma, cudaFuncAttributeMaxDynamicSharedMemorySize, SMEM_BYTES);
    convlstm_mma<<<2048, 256, SMEM_BYTES>>>(cs, hout, cout);
}